// round 1
// baseline (speedup 1.0000x reference)
#include <cuda_runtime.h>

// Cubic B-spline prefilter (Unser), DCT-II mirror boundaries.
// Implemented as a truncated symmetric FIR: h[k] = sqrt(3) * p^|k|, p = sqrt(3)-2.
// Truncation at radius 12 gives ~1e-7 relative error vs the exact IIR.

#define TPB     256
#define NAX     192          // extent of every spatial axis
#define KR      12           // FIR radius (25 taps)
#define SEGLEN  24           // outputs per thread along the filter axis
#define SEGS    (NAX / SEGLEN) // 8 segments -> 8 warps x 32 lines = 256 threads
#define WLEN    (SEGLEN + 2*KR) // 48-float register window

__device__ __forceinline__ void make_taps(float h[KR + 1]) {
    const double p = -0.26794919243112270647;  // sqrt(3) - 2
    double g = 1.73205080756887729353;         // sqrt(3) = -6p/(1-p^2)  (includes gain)
#pragma unroll
    for (int k = 0; k <= KR; ++k) { h[k] = (float)g; g *= p; }
}

__device__ __forceinline__ int mirror_idx(int i) {
    i = (i < 0) ? (-1 - i) : i;                 // half-sample left reflect
    return (i >= NAX) ? (2 * NAX - 1 - i) : i;  // half-sample right reflect
}

__device__ __forceinline__ void conv_seg(const float win[WLEN], const float h[KR + 1],
                                         float res[SEGLEN]) {
#pragma unroll
    for (int j = 0; j < SEGLEN; ++j) {
        float acc = h[0] * win[j + KR];
#pragma unroll
        for (int k = 1; k <= KR; ++k)
            acc += h[k] * (win[j + KR - k] + win[j + KR + k]);
        res[j] = acc;
    }
}

// ---------------------------------------------------------------------------
// Pass over the contiguous axis (W). Tile: 32 consecutive rows x 192 (full W).
// Transposed smem (pitch 33) makes both window reads and the store bounce
// bank-conflict-free; global loads/stores stay 128B coalesced.
// ---------------------------------------------------------------------------
__global__ __launch_bounds__(TPB) void kW(const float* __restrict__ in, float* out) {
    __shared__ float s[NAX][33];  // s[w][r]
    const int tid  = threadIdx.x;
    const int base = blockIdx.x * (32 * NAX);  // 32 rows per block

    // load + transpose (coalesced reads, conflict-free STS: stride-33 banks)
#pragma unroll 4
    for (int i = tid; i < 32 * NAX; i += TPB) {
        int r = i / NAX, w = i % NAX;
        s[w][r] = in[base + r * NAX + w];
    }
    __syncthreads();

    float h[KR + 1]; make_taps(h);
    const int r  = tid & 31;
    const int w0 = (tid >> 5) * SEGLEN;

    float win[WLEN];
#pragma unroll
    for (int j = 0; j < WLEN; ++j)
        win[j] = s[mirror_idx(w0 - KR + j)][r];  // lanes -> consecutive banks
    __syncthreads();  // all window reads in regs before overwrite

    float res[SEGLEN];
    conv_seg(win, h, res);

#pragma unroll
    for (int j = 0; j < SEGLEN; ++j) s[w0 + j][r] = res[j];
    __syncthreads();

    // coalesced store-back
#pragma unroll 4
    for (int i = tid; i < 32 * NAX; i += TPB) {
        int r2 = i / NAX, w = i % NAX;
        out[base + r2 * NAX + w] = s[w][r2];
    }
}

// ---------------------------------------------------------------------------
// Generic strided-axis pass (H: stride 192, D: stride 192*192).
// Tile: full 192 filter extent x 32 contiguous w. Safe to run in place:
// all global loads finish before __syncthreads; all stores come after.
// ---------------------------------------------------------------------------
template <int STRIDE, bool IS_D>
__global__ __launch_bounds__(TPB) void kAxis(const float* in, float* out) {
    __shared__ float s[NAX][32];
    const int tid = threadIdx.x;

    const int c = blockIdx.x % (NAX / 32);  // 6 w-chunks
    const int t = blockIdx.x / (NAX / 32);
    int base;
    if (IS_D) {
        int b  = t / NAX;
        int hh = t % NAX;
        base = b * (NAX * NAX * NAX) + hh * NAX + c * 32;
    } else {
        base = t * (NAX * NAX) + c * 32;  // t enumerates (batch, d) pairs
    }

    // coalesced load: consecutive tid -> consecutive w
#pragma unroll 4
    for (int i = tid; i < NAX * 32; i += TPB) {
        int a = i >> 5, w = i & 31;
        s[a][w] = in[base + a * STRIDE + w];
    }
    __syncthreads();

    float h[KR + 1]; make_taps(h);
    const int w  = tid & 31;
    const int a0 = (tid >> 5) * SEGLEN;

    float win[WLEN];
#pragma unroll
    for (int j = 0; j < WLEN; ++j)
        win[j] = s[mirror_idx(a0 - KR + j)][w];  // lanes: consecutive w -> one 128B row

    float res[SEGLEN];
    conv_seg(win, h, res);

#pragma unroll
    for (int j = 0; j < SEGLEN; ++j)
        out[base + (a0 + j) * STRIDE + w] = res[j];  // 128B coalesced per j
}

extern "C" void kernel_launch(void* const* d_in, const int* in_sizes, int n_in,
                              void* d_out, int out_size) {
    const float* x = (const float*)d_in[0];
    float* y = (float*)d_out;

    // (4,2,192,192,192): B = 8 fused batch*channel
    const int B = 8;
    const int rowsW   = B * NAX * NAX;            // 294912 W-lines
    const int gridW   = rowsW / 32;               // 9216
    const int gridH   = B * NAX * (NAX / 32);     // 9216
    const int gridD   = B * NAX * (NAX / 32);     // 9216

    kW<<<gridW, TPB>>>(x, y);                         // W axis: d_in -> d_out
    kAxis<NAX,        false><<<gridH, TPB>>>(y, y);   // H axis: in place
    kAxis<NAX * NAX,  true ><<<gridD, TPB>>>(y, y);   // D axis: in place
}

// round 2
// speedup vs baseline: 1.5931x; 1.5931x over previous
#include <cuda_runtime.h>

// Cubic B-spline prefilter (Unser), DCT-II mirror boundaries, as a truncated
// symmetric FIR: h[k] = sqrt(3) * p^|k|, p = sqrt(3)-2, radius 9 (19 taps).
// Pass 1: fused W+H on (192x192) slices held entirely in smem.
// Pass 2: D axis, in place.

#define NAX     192
#define KR      9
#define NT      (2*KR + 1)          // 19 taps
#define SEGLEN  24
#define WLEN    (SEGLEN + 2*KR)     // 42
#define PITCH   193                 // smem pitch (odd -> conflict-free columns)
#define TPBF    768
#define TPBD    256

// taps T[k] = sqrt(3)*p^|k-9| as compile-time constants -> FFMA-imm in SASS
#define DECL_TAPS const float T[NT] = { \
    -1.2331857e-05f,  4.6023591e-05f, -1.7176214e-04f,  6.4101700e-04f, \
    -2.3923400e-03f,  8.9283334e-03f, -3.3320997e-02f,  1.2435565e-01f, \
    -4.6410161e-01f,  1.7320508e+00f, -4.6410161e-01f,  1.2435565e-01f, \
    -3.3320997e-02f,  8.9283334e-03f, -2.3923400e-03f,  6.4101700e-04f, \
    -1.7176214e-04f,  4.6023591e-05f, -1.2331857e-05f }

__device__ __forceinline__ int mirror_idx(int i) {
    i = (i < 0) ? (-1 - i) : i;                  // half-sample left reflect
    return (i >= NAX) ? (2 * NAX - 1 - i) : i;   // half-sample right reflect
}

// ---------------------------------------------------------------------------
// Fused W+H pass. One block per (h,w) slice; slice resident in smem.
// Phase partitioning: W tasks are row-local (partition rows 0-95 / 96-191),
// H tasks are column-local (partition cols 0-95 / 96-191), so sub-phases of
// the same filter need no barrier between each other's loads and stores.
// ---------------------------------------------------------------------------
__global__ __launch_bounds__(TPBF, 1) void kWH(const float* __restrict__ in,
                                               float* __restrict__ out) {
    extern __shared__ float s[];
    const int t   = threadIdx.x;
    const int tw  = t % NAX;      // 0..191
    const int th4 = t / NAX;      // 0..3
    const int base = blockIdx.x * (NAX * NAX);

    // load slice (coalesced; conflict-free STS)
#pragma unroll
    for (int k = 0; k < NAX / 4; ++k)
        s[(4 * k + th4) * PITCH + tw] = in[base + (4 * k + th4) * NAX + tw];
    __syncthreads();

    DECL_TAPS;
    const int lane96 = t % 96;
    const int seg    = t / 96;          // 0..7
    const int o0     = seg * SEGLEN;

    // ---- W filter (along w, row-local) ----
#pragma unroll 1
    for (int p = 0; p < 2; ++p) {
        const int h = 96 * p + lane96;
        float win[WLEN];
#pragma unroll
        for (int j = 0; j < WLEN; ++j)
            win[j] = s[h * PITCH + mirror_idx(o0 - KR + j)];  // stride-193 banks: conflict-free
        float res[SEGLEN];
#pragma unroll
        for (int j = 0; j < SEGLEN; ++j) {
            float acc = 0.0f;
#pragma unroll
            for (int k = 0; k < NT; ++k) acc = fmaf(T[k], win[j + k], acc);
            res[j] = acc;
        }
        __syncthreads();                 // all reads of this phase's rows done
#pragma unroll
        for (int j = 0; j < SEGLEN; ++j) s[h * PITCH + o0 + j] = res[j];
    }
    __syncthreads();                     // W fully written before H reads

    // ---- H filter (along h, column-local) ----
#pragma unroll 1
    for (int p = 0; p < 2; ++p) {
        const int w = 96 * p + lane96;
        float win[WLEN];
#pragma unroll
        for (int j = 0; j < WLEN; ++j)
            win[j] = s[mirror_idx(o0 - KR + j) * PITCH + w];  // stride-1: conflict-free
        float res[SEGLEN];
#pragma unroll
        for (int j = 0; j < SEGLEN; ++j) {
            float acc = 0.0f;
#pragma unroll
            for (int k = 0; k < NT; ++k) acc = fmaf(T[k], win[j + k], acc);
            res[j] = acc;
        }
        __syncthreads();
#pragma unroll
        for (int j = 0; j < SEGLEN; ++j) s[(o0 + j) * PITCH + w] = res[j];
    }
    __syncthreads();

    // store slice (coalesced)
#pragma unroll
    for (int k = 0; k < NAX / 4; ++k)
        out[base + (4 * k + th4) * NAX + tw] = s[(4 * k + th4) * PITCH + tw];
}

// ---------------------------------------------------------------------------
// D pass (stride 192*192), in place. Tile: 192(d) x 32(w). All global loads
// complete before the barrier; stores go straight to gmem (block-disjoint).
// ---------------------------------------------------------------------------
__global__ __launch_bounds__(TPBD, 4) void kD(float* buf) {
    __shared__ float s[NAX][32];
    const int tid = threadIdx.x;
    const int c  = blockIdx.x % (NAX / 32);
    const int tt = blockIdx.x / (NAX / 32);
    const int b  = tt / NAX;
    const int hh = tt % NAX;
    const int base = b * (NAX * NAX * NAX) + hh * NAX + c * 32;

    const int w  = tid & 31;
    const int a4 = tid >> 5;          // 0..7
    // full unroll -> 24 outstanding LDG per thread (MLP saturates DRAM)
#pragma unroll
    for (int k = 0; k < NAX / 8; ++k)
        s[a4 + 8 * k][w] = buf[base + (a4 + 8 * k) * (NAX * NAX) + w];
    __syncthreads();

    DECL_TAPS;
    const int a0 = (tid >> 5) * SEGLEN;
    float win[WLEN];
#pragma unroll
    for (int j = 0; j < WLEN; ++j)
        win[j] = s[mirror_idx(a0 - KR + j)][w];

#pragma unroll
    for (int j = 0; j < SEGLEN; ++j) {
        float acc = 0.0f;
#pragma unroll
        for (int k = 0; k < NT; ++k) acc = fmaf(T[k], win[j + k], acc);
        buf[base + (a0 + j) * (NAX * NAX) + w] = acc;   // 128B coalesced per j
    }
}

extern "C" void kernel_launch(void* const* d_in, const int* in_sizes, int n_in,
                              void* d_out, int out_size) {
    const float* x = (const float*)d_in[0];
    float* y = (float*)d_out;

    const int B = 8;                         // 4 batch * 2 channel
    const int smemWH = NAX * PITCH * (int)sizeof(float);   // 148224 B

    static int attr_set = 0;
    if (!attr_set) {
        cudaFuncSetAttribute(kWH, cudaFuncAttributeMaxDynamicSharedMemorySize, smemWH);
        attr_set = 1;
    }

    kWH<<<B * NAX, TPBF, smemWH>>>(x, y);        // W+H fused: d_in -> d_out
    kD<<<B * NAX * (NAX / 32), TPBD>>>(y);       // D axis: in place
}

// round 3
// speedup vs baseline: 1.9216x; 1.2062x over previous
#include <cuda_runtime.h>

// Cubic B-spline prefilter (Unser), DCT-II mirror boundaries, as a truncated
// symmetric FIR: h[k] = sqrt(3) * p^|k|, p = sqrt(3)-2, radius 8 (17 taps).
// Pass 1: fused W+H on 192(h) x 32(w) strips (48 input cols with halo).
// Pass 2: D axis, in place.

#define NAX   192
#define KR    8
#define NT    (2*KR + 1)        // 17 taps
#define TW    32                // strip output width
#define LC    (TW + 2*KR)       // 48 loaded cols
#define P1    49                // s1 pitch
#define P2    33                // s2 pitch
#define SEGH  24                // H-phase outputs/thread
#define WLH   (SEGH + 2*KR)     // 40
#define SEGD  24
#define WLD   (SEGD + 2*KR)     // 40
#define TPB   256

// taps T[k] = sqrt(3)*p^|k-8| as compile-time floats -> FFMA-imm in SASS (rt=1)
#define DECL_TAPS const float T[NT] = { \
     4.6023585e-05f, -1.7176230e-04f,  6.4102556e-04f, -2.3923386e-03f, \
     8.9283341e-03f, -3.3320997e-02f,  1.2435565e-01f, -4.6410161e-01f, \
     1.7320508e+00f, -4.6410161e-01f,  1.2435565e-01f, -3.3320997e-02f, \
     8.9283341e-03f, -2.3923386e-03f,  6.4102556e-04f, -1.7176230e-04f, \
     4.6023585e-05f }

__device__ __forceinline__ int mirror_idx(int i) {
    i = (i < 0) ? (-1 - i) : i;                  // half-sample left reflect
    return (i >= NAX) ? (2 * NAX - 1 - i) : i;   // half-sample right reflect
}

// ---------------------------------------------------------------------------
// Fused W+H pass on a 192 x 32 strip.  smem: s1 = input (192 x 49),
// s2 = W-filtered (192 x 33).  63 KB total -> 3 blocks/SM.
// ---------------------------------------------------------------------------
__global__ __launch_bounds__(TPB, 3) void kWH(const float* __restrict__ in,
                                              float* __restrict__ out) {
    extern __shared__ float sm[];
    float* s1 = sm;                 // [192][P1]
    float* s2 = sm + NAX * P1;      // [192][P2]

    const int tid   = threadIdx.x;
    const int strip = blockIdx.x % (NAX / TW);   // 6 strips, adjacent -> L2 halo reuse
    const int slice = blockIdx.x / (NAX / TW);
    const int base  = slice * (NAX * NAX);
    const int wbase = strip * TW;

    // ---- load 192 x 48 (w-halo mirrored); coalesced LDG, ~conflict-free STS
#pragma unroll
    for (int k = 0; k < (NAX * LC) / TPB; ++k) {   // 36 iterations
        int i   = tid + TPB * k;
        int row = i / LC;
        int c   = i - row * LC;
        s1[row * P1 + c] = in[base + row * NAX + mirror_idx(wbase - KR + c)];
    }
    __syncthreads();

    DECL_TAPS;

    // ---- W filter: 384 tasks = (row 0..191) x (seg 0..1 of 16 cols) -> s2
#pragma unroll
    for (int it = 0; it < 2; ++it) {
        int t = tid + TPB * it;
        if (t < 2 * NAX) {
            int seg = t / NAX;
            int row = t - seg * NAX;
            const float* src = &s1[row * P1 + seg * 16];  // banks: 17*lane -> conflict-free
            float win[32];
#pragma unroll
            for (int m = 0; m < 32; ++m) win[m] = src[m];
            float* dst = &s2[row * P2 + seg * 16];        // banks: lane -> conflict-free
#pragma unroll
            for (int j = 0; j < 16; ++j) {
                float acc = 0.0f;
#pragma unroll
                for (int k = 0; k < NT; ++k) acc = fmaf(T[k], win[j + k], acc);
                dst[j] = acc;
            }
        }
    }
    __syncthreads();

    // ---- H filter: 256 tasks = (w 0..31) x (hseg 0..7); direct coalesced STG
    const int w    = tid & 31;
    const int hseg = tid >> 5;
    const int h0   = hseg * SEGH;

    float win[WLH];
#pragma unroll
    for (int m = 0; m < WLH; ++m)
        win[m] = s2[mirror_idx(h0 - KR + m) * P2 + w];    // lane = w -> conflict-free

    float* o = out + base + wbase + w;
#pragma unroll
    for (int j = 0; j < SEGH; ++j) {
        float acc = 0.0f;
#pragma unroll
        for (int k = 0; k < NT; ++k) acc = fmaf(T[k], win[j + k], acc);
        o[(h0 + j) * NAX] = acc;                          // 128B coalesced per j
    }
}

// ---------------------------------------------------------------------------
// D pass (stride 192*192), in place. Tile: 192(d) x 32(w).
// ---------------------------------------------------------------------------
__global__ __launch_bounds__(TPB, 5) void kD(float* buf) {
    __shared__ float s[NAX][32];
    const int tid = threadIdx.x;
    const int c   = blockIdx.x % (NAX / 32);
    const int tt  = blockIdx.x / (NAX / 32);
    const int b   = tt / NAX;
    const int hh  = tt % NAX;
    const int base = b * (NAX * NAX * NAX) + hh * NAX + c * 32;

    const int w  = tid & 31;
    const int a4 = tid >> 5;
#pragma unroll
    for (int k = 0; k < NAX / 8; ++k)   // 24 outstanding LDG/thread
        s[a4 + 8 * k][w] = buf[base + (a4 + 8 * k) * (NAX * NAX) + w];
    __syncthreads();

    DECL_TAPS;
    const int a0 = (tid >> 5) * SEGD;
    float win[WLD];
#pragma unroll
    for (int m = 0; m < WLD; ++m)
        win[m] = s[mirror_idx(a0 - KR + m)][w];

#pragma unroll
    for (int j = 0; j < SEGD; ++j) {
        float acc = 0.0f;
#pragma unroll
        for (int k = 0; k < NT; ++k) acc = fmaf(T[k], win[j + k], acc);
        buf[base + (a0 + j) * (NAX * NAX) + w] = acc;     // 128B coalesced per j
    }
}

extern "C" void kernel_launch(void* const* d_in, const int* in_sizes, int n_in,
                              void* d_out, int out_size) {
    const float* x = (const float*)d_in[0];
    float* y = (float*)d_out;

    const int B = 8;   // 4 batch * 2 channel
    const int smemWH = (NAX * P1 + NAX * P2) * (int)sizeof(float);  // 62976 B

    static int attr_set = 0;
    if (!attr_set) {
        cudaFuncSetAttribute(kWH, cudaFuncAttributeMaxDynamicSharedMemorySize, smemWH);
        attr_set = 1;
    }

    kWH<<<B * NAX * (NAX / TW), TPB, smemWH>>>(x, y);  // W+H fused: d_in -> d_out
    kD<<<B * NAX * (NAX / 32), TPB>>>(y);              // D axis: in place
}